// round 2
// baseline (speedup 1.0000x reference)
#include <cuda_runtime.h>
#include <cuda_bf16.h>

// ---------------- problem constants ----------------
#define B_  64
#define H_  512
#define W_  512
#define RAD 20
#define KSZ 41

// ---------------- Gaussian weights (compile-time) ----------------
constexpr double PHI[21] = {
    1.0,
    0.98019867, 0.92311635, 0.83527021, 0.72614903, 0.60653066,
    0.48675227, 0.37531110, 0.27803730, 0.19789870, 0.13533528,
    0.08892161, 0.05613478, 0.03404747, 0.01984109, 0.01110900,
    0.00597603, 0.00308871, 0.00153381, 0.00073181, 0.00033546
};

constexpr double ksum() {
    double s = PHI[0];
    for (int t = 1; t <= 20; ++t) s += 2.0 * PHI[t];
    return s;
}

struct W41 { float v[KSZ]; };

constexpr W41 make_w(double scale) {
    W41 w{};
    double s = ksum();
    for (int i = 0; i < KSZ; ++i) {
        int t = i - RAD; if (t < 0) t = -t;
        w.v[i] = (float)(scale * PHI[t] / s);
    }
    return w;
}

__device__ constexpr W41 WH = make_w(1.0);    // h-pass
__device__ constexpr W41 WV = make_w(100.0);  // v-pass folds 2*ALPHA; subtract ALPHA after

// ---------------- interleaved scratch: (dx,dy) pairs ----------------
__device__ float2 g_t[(size_t)B_ * H_ * W_];

__device__ __forceinline__ int reflect_once(int i, int n) {
    i = (i < 0) ? (-1 - i) : i;
    return (i >= n) ? (2 * n - 1 - i) : i;
}

// fast reflect for gather coords: valid for i in [-512, 1023], n=512
__device__ __forceinline__ int reflect_fast(int i) {
    return ((unsigned)i < (unsigned)W_) ? i : (~i & (2 * W_ - 1));
}

// ---------------- kernel 1: horizontal blur, both fields interleaved ----------------
// 128 threads = 2 rows x 64 threads; 8 px per thread.
__global__ __launch_bounds__(128) void hblur_kernel(
    const float* __restrict__ rdx, const float* __restrict__ rdy)
{
    __shared__ float2 s[2][W_ + 2 * RAD];   // 2 x 552 x 8B = 8832B

    const int ty = threadIdx.x >> 6;        // row within block (0/1)
    const int tx = threadIdx.x & 63;
    const int row = blockIdx.x * 2 + ty;    // 0 .. B*H-1
    const size_t rbase = (size_t)row * W_;
    const float* p0 = rdx + rbase;
    const float* p1 = rdy + rbase;

    for (int i = tx; i < W_ + 2 * RAD; i += 64) {
        int c = reflect_once(i - RAD, W_);
        s[ty][i] = make_float2(p0[c], p1[c]);
    }
    __syncthreads();

    const int x0 = tx * 8;
    float ax[8] = {0,0,0,0,0,0,0,0};
    float ay[8] = {0,0,0,0,0,0,0,0};

    // window: s[ty][x0 + k], k = 0..47 ; 24 x LDS.128 (2 float2 each)
    #pragma unroll
    for (int m = 0; m < 24; ++m) {
        const float4 q = *(const float4*)&s[ty][x0 + 2 * m];
        const int k0 = 2 * m, k1 = 2 * m + 1;
        #pragma unroll
        for (int j = 0; j < 8; ++j) {
            const int t0 = k0 - j;
            if (t0 >= 0 && t0 < KSZ) {
                ax[j] = fmaf(q.x, WH.v[t0], ax[j]);
                ay[j] = fmaf(q.y, WH.v[t0], ay[j]);
            }
            const int t1 = k1 - j;
            if (t1 >= 0 && t1 < KSZ) {
                ax[j] = fmaf(q.z, WH.v[t1], ax[j]);
                ay[j] = fmaf(q.w, WH.v[t1], ay[j]);
            }
        }
    }

    float4* o = (float4*)&g_t[rbase + x0];
    o[0] = make_float4(ax[0], ay[0], ax[1], ay[1]);
    o[1] = make_float4(ax[2], ay[2], ax[3], ay[3]);
    o[2] = make_float4(ax[4], ay[4], ax[5], ay[5]);
    o[3] = make_float4(ax[6], ay[6], ax[7], ay[7]);
}

// ---------------- kernel 2: vertical blur + warp, fused ----------------
// block (32,4) = 128 threads; tile 32 cols x 32 rows; 8 rows per thread.
// smem transposed per-column: s[col * STR2 + row], STR2=74 float2 (pad 2)
// -> LDS.128 down a column, conflict-free phases (tx*148 mod 32 period-8 distinct).
#define STR2 74

__global__ __launch_bounds__(128) void vwarp_kernel(
    const float* __restrict__ img, float* __restrict__ out)
{
    __shared__ float2 s[32 * STR2];   // 18,944B

    const int tx = threadIdx.x;       // col 0..31
    const int ty = threadIdx.y;       // 0..3
    const int x  = blockIdx.x * 32 + tx;
    const int y0 = blockIdx.y * 32;
    const int b  = blockIdx.z;
    const size_t base = (size_t)b * H_ * W_;
    const float2* gt = g_t + base;

    // halo: 72 rows of this block's 32 columns
    for (int j = ty; j < 32 + 2 * RAD; j += 4) {
        int y = reflect_once(y0 + j - RAD, H_);
        s[tx * STR2 + j] = __ldg(&gt[(size_t)y * W_ + x]);
    }
    __syncthreads();

    const int r0 = ty * 8;            // first output row (tile-local)
    float ax[8] = {0,0,0,0,0,0,0,0};
    float ay[8] = {0,0,0,0,0,0,0,0};

    // window rows r0 .. r0+47 ; 24 x LDS.128
    #pragma unroll
    for (int m = 0; m < 24; ++m) {
        const float4 q = *(const float4*)&s[tx * STR2 + r0 + 2 * m];
        // q = (dx[i], dy[i], dx[i+1], dy[i+1]) at i = r0 + 2m
        const int k0 = 2 * m, k1 = 2 * m + 1;
        #pragma unroll
        for (int j = 0; j < 8; ++j) {
            const int t0 = k0 - j;
            if (t0 >= 0 && t0 < KSZ) {
                ax[j] = fmaf(q.x, WV.v[t0], ax[j]);
                ay[j] = fmaf(q.y, WV.v[t0], ay[j]);
            }
            const int t1 = k1 - j;
            if (t1 >= 0 && t1 < KSZ) {
                ax[j] = fmaf(q.z, WV.v[t1], ax[j]);
                ay[j] = fmaf(q.w, WV.v[t1], ay[j]);
            }
        }
    }

    const float* im = img + base;
    const float xbase = (float)x - 50.0f;     // fold (2*ALPHA*blur - ALPHA)

    #pragma unroll
    for (int j = 0; j < 8; ++j) {
        const int yo = y0 + r0 + j;
        const float xx = xbase + ax[j];
        const float yy = (float)yo - 50.0f + ay[j];

        const int xi = __float2int_rd(xx);
        const int yi = __float2int_rd(yy);
        const float wx = xx - (float)xi;
        const float wy = yy - (float)yi;

        const int x0r = reflect_fast(xi);
        const int x1r = reflect_fast(xi + 1);
        const int y0r = reflect_fast(yi);     // H_==W_==512
        const int y1r = reflect_fast(yi + 1);

        const float* ra = im + (size_t)y0r * W_;
        const float* rb = im + (size_t)y1r * W_;
        const float v00 = __ldg(ra + x0r);
        const float v01 = __ldg(ra + x1r);
        const float v10 = __ldg(rb + x0r);
        const float v11 = __ldg(rb + x1r);

        const float top = fmaf(wx, v01 - v00, v00);
        const float bot = fmaf(wx, v11 - v10, v10);
        out[base + (size_t)yo * W_ + x] = fmaf(wy, bot - top, top);
    }
}

// ---------------- launch ----------------
extern "C" void kernel_launch(void* const* d_in, const int* in_sizes, int n_in,
                              void* d_out, int out_size)
{
    const float* x       = (const float*)d_in[0];  // [B,1,H,W]
    const float* rand_dx = (const float*)d_in[1];  // [B,H,W]
    const float* rand_dy = (const float*)d_in[2];  // [B,H,W]
    float* out = (float*)d_out;

    hblur_kernel<<<B_ * H_ / 2, 128>>>(rand_dx, rand_dy);

    dim3 grid(W_ / 32, H_ / 32, B_);
    dim3 block(32, 4);
    vwarp_kernel<<<grid, block>>>(x, out);
}

// round 3
// speedup vs baseline: 1.1523x; 1.1523x over previous
#include <cuda_runtime.h>
#include <cuda_bf16.h>

// ---------------- problem constants ----------------
#define B_  64
#define H_  512
#define W_  512
#define RAD 20
#define KSZ 41

// ---------------- Gaussian weights (compile-time) ----------------
constexpr double PHI[21] = {
    1.0,
    0.98019867, 0.92311635, 0.83527021, 0.72614903, 0.60653066,
    0.48675227, 0.37531110, 0.27803730, 0.19789870, 0.13533528,
    0.08892161, 0.05613478, 0.03404747, 0.01984109, 0.01110900,
    0.00597603, 0.00308871, 0.00153381, 0.00073181, 0.00033546
};

constexpr double ksum() {
    double s = PHI[0];
    for (int t = 1; t <= 20; ++t) s += 2.0 * PHI[t];
    return s;
}

struct W41x2 { float2 v[KSZ]; };

constexpr W41x2 make_w2(double scale) {
    W41x2 w{};
    double s = ksum();
    for (int i = 0; i < KSZ; ++i) {
        int t = i - RAD; if (t < 0) t = -t;
        float f = (float)(scale * PHI[t] / s);
        w.v[i].x = f; w.v[i].y = f;
    }
    return w;
}

__constant__ W41x2 WH2 = make_w2(1.0);    // h-pass
__constant__ W41x2 WV2 = make_w2(100.0);  // v-pass folds 2*ALPHA; subtract ALPHA later

// packed f32x2 FMA (sm_100+): acc = v * w + acc, elementwise fp32
__device__ __forceinline__ void fma2(float2& acc, const float2 v, const float2 w) {
    asm("fma.rn.f32x2 %0, %1, %2, %0;"
        : "+l"(reinterpret_cast<unsigned long long&>(acc))
        : "l"(reinterpret_cast<const unsigned long long&>(v)),
          "l"(reinterpret_cast<const unsigned long long&>(w)));
}

// ---------------- interleaved scratch: (dx,dy) pairs ----------------
__device__ float2 g_t[(size_t)B_ * H_ * W_];

__device__ __forceinline__ int reflect_once(int i, int n) {
    i = (i < 0) ? (-1 - i) : i;
    return (i >= n) ? (2 * n - 1 - i) : i;
}

// fast reflect for gather coords: valid for i in [-512, 1023], n=512
__device__ __forceinline__ int reflect_fast(int i) {
    return ((unsigned)i < (unsigned)W_) ? i : (~i & (2 * W_ - 1));
}

// ================= kernel 1: horizontal blur =================
// Tile: 32 rows x 64 cols. block (32,8): threadIdx.x = row lane, threadIdx.y = col chunk.
// smem s[c*33 + r] (c = 0..103 window col, r = row): compute loads have 8B lane
// stride (conflict-free), halo stores 264B stride (conflict-free).
#define HS_STR 33

__global__ __launch_bounds__(256) void hblur_kernel(
    const float* __restrict__ rdx, const float* __restrict__ rdy)
{
    __shared__ float2 s[104 * HS_STR];   // 27,456 B

    const int r   = threadIdx.x;              // 0..31 row lane
    const int ty  = threadIdx.y;              // 0..7 col chunk
    const int tid = ty * 32 + r;
    const int c0   = blockIdx.x * 64;         // first output col
    const int row0 = blockIdx.y * 32;         // first row
    const int b    = blockIdx.z;
    const size_t base = (size_t)b * H_ * W_;

    // halo load: 104 window cols x 32 rows, coalesced on c
    for (int i = tid; i < 104 * 32; i += 256) {
        const int rr = i / 104;
        const int cc = i % 104;
        const int gc = reflect_once(c0 - RAD + cc, W_);
        const size_t g = base + (size_t)(row0 + rr) * W_ + gc;
        s[cc * HS_STR + rr] = make_float2(rdx[g], rdy[g]);
    }
    __syncthreads();

    const int x0 = ty * 8;                    // local first output col
    float2 acc[8] = {};
    float2 win[8];
    #pragma unroll
    for (int k = 0; k < 8; ++k) win[k] = s[(x0 + k) * HS_STR + r];

    #pragma unroll
    for (int t = 0; t < KSZ; ++t) {
        const float2 w = WH2.v[t];
        #pragma unroll
        for (int j = 0; j < 8; ++j)
            fma2(acc[j], win[(t + j) & 7], w);
        if (t < KSZ - 1)
            win[t & 7] = s[(x0 + t + 8) * HS_STR + r];
    }
    __syncthreads();

    // transpose through smem for coalesced global stores
    float2* s2 = s;                           // reuse, layout s2[r*65 + c]
    #pragma unroll
    for (int j = 0; j < 8; ++j)
        s2[r * 65 + x0 + j] = acc[j];
    __syncthreads();

    for (int i = tid; i < 32 * 64; i += 256) {
        const int rr = i >> 6;
        const int cc = i & 63;
        g_t[base + (size_t)(row0 + rr) * W_ + c0 + cc] = s2[rr * 65 + cc];
    }
}

// ================= kernel 2: vertical blur + warp =================
// Tile: 32 cols x 64 rows. block (32,8): tx = col, ty = row chunk (8 rows each).
// smem column-major s[tx*105 + row]: odd stride 105 -> conflict-free LDS.64.
#define VS_STR 105

__global__ __launch_bounds__(256) void vwarp_kernel(
    const float* __restrict__ img, float* __restrict__ out)
{
    __shared__ float2 s[32 * VS_STR];   // 26,880 B

    const int tx = threadIdx.x;         // col 0..31
    const int ty = threadIdx.y;         // 0..7
    const int x  = blockIdx.x * 32 + tx;
    const int y0 = blockIdx.y * 64;
    const int b  = blockIdx.z;
    const size_t base = (size_t)b * H_ * W_;
    const float2* gt = g_t + base;

    // halo: 104 rows of this block's 32 cols, coalesced on x
    for (int j = ty; j < 64 + 2 * RAD; j += 8) {
        const int y = reflect_once(y0 + j - RAD, H_);
        s[tx * VS_STR + j] = __ldg(&gt[(size_t)y * W_ + x]);
    }
    __syncthreads();

    const int r0 = ty * 8;              // first output row (tile-local)
    float2 acc[8] = {};
    float2 win[8];
    #pragma unroll
    for (int k = 0; k < 8; ++k) win[k] = s[tx * VS_STR + r0 + k];

    #pragma unroll
    for (int t = 0; t < KSZ; ++t) {
        const float2 w = WV2.v[t];
        #pragma unroll
        for (int j = 0; j < 8; ++j)
            fma2(acc[j], win[(t + j) & 7], w);
        if (t < KSZ - 1)
            win[t & 7] = s[tx * VS_STR + r0 + t + 8];
    }

    const float* im = img + base;
    const float xbase = (float)x - 50.0f;   // fold (2*ALPHA*blur - ALPHA)

    #pragma unroll
    for (int j = 0; j < 8; ++j) {
        const int yo = y0 + r0 + j;
        const float xx = xbase + acc[j].x;
        const float yy = (float)yo - 50.0f + acc[j].y;

        const int xi = __float2int_rd(xx);
        const int yi = __float2int_rd(yy);
        const float wx = xx - (float)xi;
        const float wy = yy - (float)yi;

        const int x0r = reflect_fast(xi);
        const int x1r = reflect_fast(xi + 1);
        const int y0r = reflect_fast(yi);   // H_==W_==512
        const int y1r = reflect_fast(yi + 1);

        const float* ra = im + (size_t)y0r * W_;
        const float* rb = im + (size_t)y1r * W_;
        const float v00 = __ldg(ra + x0r);
        const float v01 = __ldg(ra + x1r);
        const float v10 = __ldg(rb + x0r);
        const float v11 = __ldg(rb + x1r);

        const float top = fmaf(wx, v01 - v00, v00);
        const float bot = fmaf(wx, v11 - v10, v10);
        out[base + (size_t)yo * W_ + x] = fmaf(wy, bot - top, top);
    }
}

// ---------------- launch ----------------
extern "C" void kernel_launch(void* const* d_in, const int* in_sizes, int n_in,
                              void* d_out, int out_size)
{
    const float* x       = (const float*)d_in[0];  // [B,1,H,W]
    const float* rand_dx = (const float*)d_in[1];  // [B,H,W]
    const float* rand_dy = (const float*)d_in[2];  // [B,H,W]
    float* out = (float*)d_out;

    {
        dim3 grid(W_ / 64, H_ / 32, B_);
        dim3 block(32, 8);
        hblur_kernel<<<grid, block>>>(rand_dx, rand_dy);
    }
    {
        dim3 grid(W_ / 32, H_ / 64, B_);
        dim3 block(32, 8);
        vwarp_kernel<<<grid, block>>>(x, out);
    }
}

// round 4
// speedup vs baseline: 1.2703x; 1.1024x over previous
#include <cuda_runtime.h>
#include <cuda_bf16.h>

// ---------------- problem constants ----------------
#define B_  64
#define H_  512
#define W_  512
#define RAD 20
#define KSZ 41

// ---------------- Gaussian weights (compile-time) ----------------
constexpr double PHI[21] = {
    1.0,
    0.98019867, 0.92311635, 0.83527021, 0.72614903, 0.60653066,
    0.48675227, 0.37531110, 0.27803730, 0.19789870, 0.13533528,
    0.08892161, 0.05613478, 0.03404747, 0.01984109, 0.01110900,
    0.00597603, 0.00308871, 0.00153381, 0.00073181, 0.00033546
};

constexpr double ksum() {
    double s = PHI[0];
    for (int t = 1; t <= 20; ++t) s += 2.0 * PHI[t];
    return s;
}

struct W41x2 { float2 v[KSZ]; };

constexpr W41x2 make_w2(double scale) {
    W41x2 w{};
    double s = ksum();
    for (int i = 0; i < KSZ; ++i) {
        int t = i - RAD; if (t < 0) t = -t;
        float f = (float)(scale * PHI[t] / s);
        w.v[i].x = f; w.v[i].y = f;
    }
    return w;
}

__constant__ W41x2 WH2 = make_w2(1.0);    // h-pass
__constant__ W41x2 WV2 = make_w2(100.0);  // v-pass folds 2*ALPHA; subtract ALPHA later

// packed f32x2 FMA (sm_100+)
__device__ __forceinline__ void fma2(float2& acc, const float2 v, const float2 w) {
    asm("fma.rn.f32x2 %0, %1, %2, %0;"
        : "+l"(reinterpret_cast<unsigned long long&>(acc))
        : "l"(reinterpret_cast<const unsigned long long&>(v)),
          "l"(reinterpret_cast<const unsigned long long&>(w)));
}

// ---------------- interleaved scratch: (dx,dy) pairs ----------------
__device__ float2 g_t[(size_t)B_ * H_ * W_];

__device__ __forceinline__ int reflect_once(int i, int n) {
    i = (i < 0) ? (-1 - i) : i;
    return (i >= n) ? (2 * n - 1 - i) : i;
}

// fast reflect for gather coords: valid for i in [-512, 1023], n=512
__device__ __forceinline__ int reflect_fast(int i) {
    return ((unsigned)i < (unsigned)W_) ? i : (~i & (2 * W_ - 1));
}

// ================= kernel 1: horizontal blur =================
// Tile: 32 rows x 32 cols. block (32,4): threadIdx.x = row lane, ty = col chunk (8 cols).
// smem col-major s[cc*33 + r], cc = 0..71 window col: compute LDS.64 lane stride 8B
// (conflict-free), halo STS word-stride 66 mod 32 = 2 (conflict-free).
#define HS_STR 33

__global__ __launch_bounds__(128, 11) void hblur_kernel(
    const float* __restrict__ rdx, const float* __restrict__ rdy)
{
    __shared__ float2 s[72 * HS_STR];   // 19,008 B

    const int r   = threadIdx.x;             // 0..31 row lane
    const int ty  = threadIdx.y;             // 0..3 col chunk
    const int tid = ty * 32 + r;
    const int c0   = blockIdx.x * 32;        // first output col
    const int row0 = blockIdx.y * 32;        // first row
    const int b    = blockIdx.z;
    const size_t base = (size_t)b * H_ * W_;

    // halo: 72 window cols x 32 rows; div-free, coalesced on col
    {
        const int lc = tid & 31;             // lane col
        const int lr = tid >> 5;             // 0..3 row group
        #pragma unroll
        for (int q = 0; q < 3; ++q) {
            const int cc = lc + 32 * q;
            if (cc < 72) {
                const int gc = reflect_once(c0 - RAD + cc, W_);
                #pragma unroll
                for (int m = 0; m < 8; ++m) {
                    const int rr = lr + 4 * m;
                    const size_t g = base + (size_t)(row0 + rr) * W_ + gc;
                    s[cc * HS_STR + rr] = make_float2(rdx[g], rdy[g]);
                }
            }
        }
    }
    __syncthreads();

    const int x0 = ty * 8;                   // local first output col
    float2 acc[8] = {};
    float2 win[8];
    #pragma unroll
    for (int k = 0; k < 8; ++k) win[k] = s[(x0 + k) * HS_STR + r];

    #pragma unroll
    for (int t = 0; t < KSZ; ++t) {
        const float2 w = WH2.v[t];
        #pragma unroll
        for (int j = 0; j < 8; ++j)
            fma2(acc[j], win[(t + j) & 7], w);
        if (t < KSZ - 1)
            win[t & 7] = s[(x0 + t + 8) * HS_STR + r];
    }
    __syncthreads();

    // transpose through smem: s2[r*41 + c] (stride 41 -> 82l words mod 32, conflict-free)
    float2* s2 = s;
    #pragma unroll
    for (int j = 0; j < 8; ++j)
        s2[r * 41 + x0 + j] = acc[j];
    __syncthreads();

    // coalesced stores: 32x32 tile, 8 iterations
    #pragma unroll
    for (int m = 0; m < 8; ++m) {
        const int i  = m * 128 + tid;
        const int rr = i >> 5;
        const int cc = i & 31;
        g_t[base + (size_t)(row0 + rr) * W_ + c0 + cc] = s2[rr * 41 + cc];
    }
}

// ================= kernel 2: vertical blur + warp =================
// Tile: 32 cols x 32 rows. block (32,4): tx = col, ty = row chunk (8 rows).
// smem col-major s[tx*73 + row]: word-stride 146 mod 32 = 18, gcd(18,32)=2
// -> conflict-free LDS.64/STS.64.
#define VS_STR 73

__global__ __launch_bounds__(128, 11) void vwarp_kernel(
    const float* __restrict__ img, float* __restrict__ out)
{
    __shared__ float2 s[32 * VS_STR];   // 18,688 B

    const int tx = threadIdx.x;         // col 0..31
    const int ty = threadIdx.y;         // 0..3
    const int x  = blockIdx.x * 32 + tx;
    const int y0 = blockIdx.y * 32;
    const int b  = blockIdx.z;
    const size_t base = (size_t)b * H_ * W_;
    const float2* gt = g_t + base;

    // halo: 72 rows of this block's 32 cols, coalesced on x; 18 iters
    #pragma unroll
    for (int j = ty; j < 32 + 2 * RAD; j += 4) {
        const int y = reflect_once(y0 + j - RAD, H_);
        s[tx * VS_STR + j] = __ldg(&gt[(size_t)y * W_ + x]);
    }
    __syncthreads();

    const int r0 = ty * 8;              // first output row (tile-local)
    float2 acc[8] = {};
    float2 win[8];
    #pragma unroll
    for (int k = 0; k < 8; ++k) win[k] = s[tx * VS_STR + r0 + k];

    #pragma unroll
    for (int t = 0; t < KSZ; ++t) {
        const float2 w = WV2.v[t];
        #pragma unroll
        for (int j = 0; j < 8; ++j)
            fma2(acc[j], win[(t + j) & 7], w);
        if (t < KSZ - 1)
            win[t & 7] = s[tx * VS_STR + r0 + t + 8];
    }

    const float* im = img + base;
    const float xbase = (float)x - 50.0f;   // fold (2*ALPHA*blur - ALPHA)

    #pragma unroll
    for (int j = 0; j < 8; ++j) {
        const int yo = y0 + r0 + j;
        const float xx = xbase + acc[j].x;
        const float yy = (float)yo - 50.0f + acc[j].y;

        const int xi = __float2int_rd(xx);
        const int yi = __float2int_rd(yy);
        const float wx = xx - (float)xi;
        const float wy = yy - (float)yi;

        const int x0r = reflect_fast(xi);
        const int x1r = reflect_fast(xi + 1);
        const int y0r = reflect_fast(yi);   // H_==W_==512
        const int y1r = reflect_fast(yi + 1);

        const float* ra = im + (size_t)y0r * W_;
        const float* rb = im + (size_t)y1r * W_;
        const float v00 = __ldg(ra + x0r);
        const float v01 = __ldg(ra + x1r);
        const float v10 = __ldg(rb + x0r);
        const float v11 = __ldg(rb + x1r);

        const float top = fmaf(wx, v01 - v00, v00);
        const float bot = fmaf(wx, v11 - v10, v10);
        out[base + (size_t)yo * W_ + x] = fmaf(wy, bot - top, top);
    }
}

// ---------------- launch ----------------
extern "C" void kernel_launch(void* const* d_in, const int* in_sizes, int n_in,
                              void* d_out, int out_size)
{
    const float* x       = (const float*)d_in[0];  // [B,1,H,W]
    const float* rand_dx = (const float*)d_in[1];  // [B,H,W]
    const float* rand_dy = (const float*)d_in[2];  // [B,H,W]
    float* out = (float*)d_out;

    {
        dim3 grid(W_ / 32, H_ / 32, B_);
        dim3 block(32, 4);
        hblur_kernel<<<grid, block>>>(rand_dx, rand_dy);
    }
    {
        dim3 grid(W_ / 32, H_ / 32, B_);
        dim3 block(32, 4);
        vwarp_kernel<<<grid, block>>>(x, out);
    }
}